// round 6
// baseline (speedup 1.0000x reference)
#include <cuda_runtime.h>
#include <cstdint>

// CARAFE: B=8, C=256, H=W=64, K=5, UP=2.
// out[b,c,2h+i,2w+j] = sum_{ki,kj} km[b,(i*2+j)*25+ki*5+kj,h,w] * x[b,c,h+ki-2,w+kj-2]
//
// R5 changes vs R4 (80.2us):
//  - packed fma.rn.f32x2: reduction over k split into (even,odd) lanes of an
//    f32x2 accumulator. Weights pre-packed into 48 u64 regs (+4 scalar), taps
//    loaded pairwise into aligned register pairs. 100 FFMA -> 48 FMA2 + 4 FMA
//    + 4 FADD per channel => fma-pipe floor halves (~44us -> ~23us).
//  - smem ping-pong double buffer: one __syncthreads per 4-channel iteration.

namespace {
constexpr int Hc = 64, Wc = 64, Cc = 256, Bc = 8;
constexpr int Kk = 5, QQ = 100;
constexpr int CPC = 4;                 // channels per slice per stage
constexpr int NCH = 8;                 // channels staged per iteration (2 slices)
constexpr int THREADS = 128;
constexpr int SROW = 72;               // padded smem row (4 halo + 64 + 4 halo)
constexpr int NTASK = 5;               // 8ch*5r*16 float4 / 128 threads
constexpr int CHSTRIDE = NCH * SROW;   // float stride between kernel rows r
constexpr int BUFOFF = Kk * NCH * SROW; // floats per smem buffer (2880)
}

__device__ __forceinline__ unsigned long long pack2(float lo, float hi) {
    unsigned long long r;
    asm("mov.b64 %0, {%1, %2};" : "=l"(r) : "f"(lo), "f"(hi));
    return r;
}
__device__ __forceinline__ void unpack2(float& lo, float& hi, unsigned long long v) {
    asm("mov.b64 {%0, %1}, %2;" : "=f"(lo), "=f"(hi) : "l"(v));
}
__device__ __forceinline__ void fma2(unsigned long long& d,
                                     unsigned long long a, unsigned long long b) {
    asm("fma.rn.f32x2 %0, %1, %2, %0;" : "+l"(d) : "l"(a), "l"(b));
}

__global__ __launch_bounds__(THREADS, 3)
void carafe_kernel(const float* __restrict__ x,
                   const float* __restrict__ km,
                   float* __restrict__ out)
{
    const int bh = blockIdx.x;           // 0..511
    const int b  = bh >> 6;
    const int h  = bh & 63;
    const int cbase = blockIdx.y << 7;   // 0 or 128
    const int tid = threadIdx.x;
    const int w   = tid & 63;
    const int s   = tid >> 6;            // channel slice 0/1

    __shared__ float sbuf[2][Kk][NCH][SROW];   // ping-pong buffers

    // ---- zero halo/pad columns once, both buffers (cols 0..3 and 68..71) ----
    for (int e = tid; e < 2 * Kk * NCH * 8; e += THREADS) {
        int rc = e >> 3, cs = e & 7;
        int col = (cs < 4) ? cs : (64 + cs);
        (&sbuf[0][0][0][0])[rc * SROW + col] = 0.f;
    }

    // ---- this pixel's 100 weights -> 48 packed f32x2 pairs + 4 scalars ----
    // pair p of subpixel u covers taps k=2p, 2p+1 (flattened k = r*5+j)
    const float* kmp = km + ((size_t)b * QQ * Hc + h) * Wc + w;
    unsigned long long wp[4][12];
    float w24[4];
    #pragma unroll
    for (int u = 0; u < 4; u++) {
        #pragma unroll
        for (int p = 0; p < 12; p++) {
            float lo = __ldg(kmp + (size_t)(u * 25 + 2 * p    ) * (Hc * Wc));
            float hi = __ldg(kmp + (size_t)(u * 25 + 2 * p + 1) * (Hc * Wc));
            wp[u][p] = pack2(lo, hi);
        }
        w24[u] = __ldg(kmp + (size_t)(u * 25 + 24) * (Hc * Wc));
    }

    const float4* xb4 = (const float4*)(x + (size_t)b * Cc * Hc * Wc);
    float*        ob  = out + (size_t)b * Cc * (Hc * 2) * (Wc * 2);

    // ---- staging tasks: 5 fixed float4 LDG/STS per thread, set up once ----
    int  sidx[NTASK];
    bool svalid[NTASK];
    int  soff[NTASK];
    #pragma unroll
    for (int k = 0; k < NTASK; k++) {
        int e  = tid + k * THREADS;      // 0..639
        int f  = e & 15;                 // float4 column (gc = 4f)
        int rc = e >> 4;                 // 0..39
        int r  = rc >> 3;                // 0..4
        int ci = rc & 7;                 // 0..7
        int gr = h - 2 + r;
        int ch = cbase + ((ci >> 2) << 6) + (ci & 3);   // + t0 at use
        svalid[k] = (unsigned)gr < (unsigned)Hc;
        sidx[k]   = ch * (Hc * Wc / 4) + gr * (Wc / 4) + f;
        soff[k]   = (r * NCH + ci) * SROW + 4 * f + 4;
    }

    // initial prefetch (t0 = 0)
    float4 pf[NTASK];
    #pragma unroll
    for (int k = 0; k < NTASK; k++) {
        float4 v = make_float4(0.f, 0.f, 0.f, 0.f);
        if (svalid[k]) v = __ldg(xb4 + sidx[k]);
        pf[k] = v;
    }

    float* obase = ob + ((size_t)(cbase + (s << 6)) * 128 + 2 * h) * 128 + 2 * w;
    float* sb = &sbuf[0][0][0][0];
    int bufOff = 0;

    for (int t0 = 0; t0 < 64; t0 += CPC) {
        // commit prefetched tile into current buffer (other buffer still being
        // read by nobody: previous iteration's readers used the other one)
        #pragma unroll
        for (int k = 0; k < NTASK; k++)
            *reinterpret_cast<float4*>(sb + bufOff + soff[k]) = pf[k];
        __syncthreads();

        // prefetch next tile (overlaps compute)
        if (t0 + CPC < 64) {
            #pragma unroll
            for (int k = 0; k < NTASK; k++) {
                sidx[k] += CPC * (Hc * Wc / 4);
                float4 v = make_float4(0.f, 0.f, 0.f, 0.f);
                if (svalid[k]) v = __ldg(xb4 + sidx[k]);
                pf[k] = v;
            }
        }

        // ---- compute CPC channels for this thread's slice ----
        const float* base = sb + bufOff + (s * CPC) * SROW + (w + 2);
        #pragma unroll
        for (int kch = 0; kch < CPC; kch++) {
            const float* sp = base + kch * SROW;
            unsigned long long a0 = 0ull, a1 = 0ull, a2 = 0ull, a3 = 0ull;
            #pragma unroll
            for (int p = 0; p < 12; p++) {
                const int k0 = 2 * p, k1 = 2 * p + 1;
                float xl = sp[(k0 / 5) * CHSTRIDE + (k0 % 5)];
                float xh = sp[(k1 / 5) * CHSTRIDE + (k1 % 5)];
                unsigned long long xp = pack2(xl, xh);
                fma2(a0, wp[0][p], xp);
                fma2(a1, wp[1][p], xp);
                fma2(a2, wp[2][p], xp);
                fma2(a3, wp[3][p], xp);
            }
            float x24 = sp[4 * CHSTRIDE + 4];

            float l, hgh, r0, r1, r2, r3;
            unpack2(l, hgh, a0); r0 = fmaf(w24[0], x24, l + hgh);
            unpack2(l, hgh, a1); r1 = fmaf(w24[1], x24, l + hgh);
            unpack2(l, hgh, a2); r2 = fmaf(w24[2], x24, l + hgh);
            unpack2(l, hgh, a3); r3 = fmaf(w24[3], x24, l + hgh);

            // subpixel u = i*2+j -> (2h+i, 2w+j)
            float* o = obase + (size_t)(t0 + kch) * (128 * 128);
            *reinterpret_cast<float2*>(o)       = make_float2(r0, r1);
            *reinterpret_cast<float2*>(o + 128) = make_float2(r2, r3);
        }
        bufOff ^= BUFOFF;
        __syncthreads();   // readers done before next commit overwrites... 
        // NOTE: with ping-pong the next commit targets the OTHER buffer, so this
        // barrier protects only the 2-iterations-apart reuse; it is required
        // because commit(i+2) writes the buffer read in iteration i.
    }
}

extern "C" void kernel_launch(void* const* d_in, const int* in_sizes, int n_in,
                              void* d_out, int out_size)
{
    const float* x  = (const float*)d_in[0];   // [8,256,64,64]
    const float* km = (const float*)d_in[1];   // [8,100,64,64]
    float* out = (float*)d_out;                // [8,256,128,128]

    dim3 grid(Bc * Hc, 2);
    carafe_kernel<<<grid, THREADS>>>(x, km, out);
}

// round 7
// speedup vs baseline: 1.8259x; 1.8259x over previous
#include <cuda_runtime.h>
#include <cstdint>

// CARAFE: B=8, C=256, H=W=64, K=5, UP=2.
// out[b,c,2h+i,2w+j] = sum_{ki,kj} km[b,(i*2+j)*25+ki*5+kj,h,w] * x[b,c,h+ki-2,w+kj-2]
//
// R6 vs R4 (80.2us):  [R5 f32x2 experiment regressed -> reverted to scalar FFMA]
//  - staging via cp.async.cg 16B with zero-fill (src-size=0 for invalid halo
//    rows): no pf[] register buffer, no STS -> ~20 fewer regs
//  - __launch_bounds__(128,4): 4 CTAs/SM (16 warps) instead of 3 (12 warps)
//  - smem ping-pong + commit_group/wait_group double buffering

namespace {
constexpr int Hc = 64, Wc = 64, Cc = 256, Bc = 8;
constexpr int Kk = 5, QQ = 100;
constexpr int CPC = 4;                  // channels per slice per stage
constexpr int NCH = 8;                  // channels staged per iteration (2 slices)
constexpr int THREADS = 128;
constexpr int SROW = 72;                // padded smem row (4 halo + 64 + 4 halo)
constexpr int NTASK = 5;                // 8ch*5rows*16 float4 / 128 threads
constexpr int BUFFLOATS = Kk * NCH * SROW;        // 2880 floats per buffer
constexpr int BUFBYTES  = BUFFLOATS * 4;          // 11520 B
}

__device__ __forceinline__ void cp_async16(uint32_t dst, const float4* src, bool valid) {
    int sz = valid ? 16 : 0;
    asm volatile("cp.async.cg.shared.global [%0], [%1], 16, %2;"
                 :: "r"(dst), "l"(src), "r"(sz) : "memory");
}
__device__ __forceinline__ void cp_commit() {
    asm volatile("cp.async.commit_group;" ::: "memory");
}
template <int N>
__device__ __forceinline__ void cp_wait() {
    asm volatile("cp.async.wait_group %0;" :: "n"(N) : "memory");
}

__global__ __launch_bounds__(THREADS, 4)
void carafe_kernel(const float* __restrict__ x,
                   const float* __restrict__ km,
                   float* __restrict__ out)
{
    const int bh = blockIdx.x;           // 0..511
    const int b  = bh >> 6;
    const int h  = bh & 63;
    const int cbase = blockIdx.y << 7;   // 0 or 128
    const int tid = threadIdx.x;
    const int w   = tid & 63;
    const int s   = tid >> 6;            // channel slice 0/1

    __shared__ __align__(16) float sbuf[2][Kk][NCH][SROW];   // ping-pong

    // ---- zero halo/pad columns once, both buffers (cols 0..3, 68..71) ----
    for (int e = tid; e < 2 * Kk * NCH * 8; e += THREADS) {
        int rc = e >> 3, cs = e & 7;
        int col = (cs < 4) ? cs : (64 + cs);
        (&sbuf[0][0][0][0])[rc * SROW + col] = 0.f;
    }

    // ---- this pixel's 100 reassembly weights -> registers ----
    float wreg[QQ];
    const float* kmp = km + ((size_t)b * QQ * Hc + h) * Wc + w;
    #pragma unroll
    for (int q = 0; q < QQ; q++)
        wreg[q] = __ldg(kmp + (size_t)q * (Hc * Wc));

    const float4* xb4 = (const float4*)(x + (size_t)b * Cc * Hc * Wc);
    float*        ob  = out + (size_t)b * Cc * (Hc * 2) * (Wc * 2);

    // ---- staging tasks: 5 fixed cp.async(16B) per thread, set up once ----
    const uint32_t sb_u32 = (uint32_t)__cvta_generic_to_shared(&sbuf[0][0][0][0]);
    int      sidx[NTASK];     // global float4 index (advances by 4 channels/iter)
    uint32_t sdst[NTASK];     // smem byte address within buffer 0
    bool     svalid[NTASK];
    #pragma unroll
    for (int k = 0; k < NTASK; k++) {
        int e  = tid + k * THREADS;      // 0..639
        int f  = e & 15;                 // float4 column (gc = 4f)
        int rc = e >> 4;                 // 0..39
        int r  = rc >> 3;                // 0..4
        int ci = rc & 7;                 // 0..7
        int gr = h - 2 + r;
        int ch = cbase + ((ci >> 2) << 6) + (ci & 3);   // + t0 at use
        svalid[k] = (unsigned)gr < (unsigned)Hc;
        sidx[k]   = ch * (Hc * Wc / 4) + gr * (Wc / 4) + f;
        sdst[k]   = sb_u32 + ((r * NCH + ci) * SROW + 4 * f + 4) * 4;
    }

    // prologue: stage t0=0 into buffer 0
    #pragma unroll
    for (int k = 0; k < NTASK; k++)
        cp_async16(sdst[k], xb4 + sidx[k], svalid[k]);
    cp_commit();

    float* obase = ob + ((size_t)(cbase + (s << 6)) * 128 + 2 * h) * 128 + 2 * w;
    const float* sbgen = &sbuf[0][0][0][0];
    int bufOff = 0;            // float offset of current buffer
    uint32_t dstOff = BUFBYTES;  // byte offset of NEXT buffer

    for (int t0 = 0; t0 < 64; t0 += CPC) {
        // issue next tile into the other buffer, then wait for current tile
        if (t0 + CPC < 64) {
            #pragma unroll
            for (int k = 0; k < NTASK; k++) {
                sidx[k] += CPC * (Hc * Wc / 4);
                cp_async16(sdst[k] + dstOff, xb4 + sidx[k], svalid[k]);
            }
            cp_commit();
            cp_wait<1>();      // current buffer's group complete; next in flight
        } else {
            cp_wait<0>();
        }
        __syncthreads();

        // ---- compute CPC channels for this thread's slice (scalar FFMA) ----
        const float* base = sbgen + bufOff + (s * CPC) * SROW + (w + 2);
        #pragma unroll
        for (int kch = 0; kch < CPC; kch++) {
            const float* sp = base + kch * SROW;
            float a0 = 0.f, a1 = 0.f, a2 = 0.f, a3 = 0.f;
            #pragma unroll
            for (int r = 0; r < Kk; r++) {
                const float* rp = sp + r * (NCH * SROW);
                float x0 = rp[0], x1 = rp[1], x2 = rp[2], x3 = rp[3], x4 = rp[4];
                const int wb = r * Kk;
                a0 = fmaf(wreg[wb+0],    x0, a0); a0 = fmaf(wreg[wb+1],    x1, a0);
                a0 = fmaf(wreg[wb+2],    x2, a0); a0 = fmaf(wreg[wb+3],    x3, a0);
                a0 = fmaf(wreg[wb+4],    x4, a0);
                a1 = fmaf(wreg[25+wb+0], x0, a1); a1 = fmaf(wreg[25+wb+1], x1, a1);
                a1 = fmaf(wreg[25+wb+2], x2, a1); a1 = fmaf(wreg[25+wb+3], x3, a1);
                a1 = fmaf(wreg[25+wb+4], x4, a1);
                a2 = fmaf(wreg[50+wb+0], x0, a2); a2 = fmaf(wreg[50+wb+1], x1, a2);
                a2 = fmaf(wreg[50+wb+2], x2, a2); a2 = fmaf(wreg[50+wb+3], x3, a2);
                a2 = fmaf(wreg[50+wb+4], x4, a2);
                a3 = fmaf(wreg[75+wb+0], x0, a3); a3 = fmaf(wreg[75+wb+1], x1, a3);
                a3 = fmaf(wreg[75+wb+2], x2, a3); a3 = fmaf(wreg[75+wb+3], x3, a3);
                a3 = fmaf(wreg[75+wb+4], x4, a3);
            }
            // subpixel u = i*2+j -> (2h+i, 2w+j)
            float* o = obase + (size_t)(t0 + kch) * (128 * 128);
            *reinterpret_cast<float2*>(o)       = make_float2(a0, a1);
            *reinterpret_cast<float2*>(o + 128) = make_float2(a2, a3);
        }

        bufOff ^= BUFFLOATS;
        dstOff ^= BUFBYTES;
        __syncthreads();   // readers of this buffer done before it is re-filled
    }
}

extern "C" void kernel_launch(void* const* d_in, const int* in_sizes, int n_in,
                              void* d_out, int out_size)
{
    const float* x  = (const float*)d_in[0];   // [8,256,64,64]
    const float* km = (const float*)d_in[1];   // [8,100,64,64]
    float* out = (float*)d_out;                // [8,256,128,128]

    dim3 grid(Bc * Hc, 2);
    carafe_kernel<<<grid, THREADS>>>(x, km, out);
}

// round 8
// speedup vs baseline: 1.8833x; 1.0314x over previous
#include <cuda_runtime.h>
#include <cstdint>

// CARAFE: B=8, C=256, H=W=64, K=5, UP=2.
// out[b,c,2h+i,2w+j] = sum_{ki,kj} km[b,(i*2+j)*25+ki*5+kj,h,w] * x[b,c,h+ki-2,w+kj-2]
//
// R7 vs R6 (62.0us):
//  - 3-deep cp.async pipeline -> ONE __syncthreads per 4-channel iteration
//    (group t -> buf[t%3]; buf reused at i+2 was read at i-1; the iter-i sync
//     after wait_group separates those readers from the new writer)
//  - staging groups 0 and 1 issued BEFORE the 100-weight LDG prologue
//  - strength-reduced output pointer walk
// Compute loop unchanged: 25 LDS + 100 scalar FFMA per channel, weights in regs.

namespace {
constexpr int Hc = 64, Wc = 64, Cc = 256, Bc = 8;
constexpr int Kk = 5, QQ = 100;
constexpr int CPC = 4;                  // channels per slice per stage
constexpr int NCH = 8;                  // channels staged per iteration (2 slices)
constexpr int THREADS = 128;
constexpr int SROW = 72;                // padded smem row (4 halo + 64 + 4 halo)
constexpr int NTASK = 5;                // 8ch*5rows*16 float4 / 128 threads
constexpr int NBUF = 3;
constexpr int BUFFLOATS = Kk * NCH * SROW;        // 2880 floats per buffer
constexpr int BUFBYTES  = BUFFLOATS * 4;          // 11520 B
constexpr int NITER = 64 / CPC;                   // 16
constexpr int CH4STRIDE = CPC * (Hc * Wc / 4);    // float4 stride of CPC channels
}

__device__ __forceinline__ void cp_async16(uint32_t dst, const float4* src, bool valid) {
    int sz = valid ? 16 : 0;
    asm volatile("cp.async.cg.shared.global [%0], [%1], 16, %2;"
                 :: "r"(dst), "l"(src), "r"(sz) : "memory");
}
__device__ __forceinline__ void cp_commit() {
    asm volatile("cp.async.commit_group;" ::: "memory");
}
template <int N>
__device__ __forceinline__ void cp_wait() {
    asm volatile("cp.async.wait_group %0;" :: "n"(N) : "memory");
}

__global__ __launch_bounds__(THREADS, 4)
void carafe_kernel(const float* __restrict__ x,
                   const float* __restrict__ km,
                   float* __restrict__ out)
{
    const int bh = blockIdx.x;           // 0..511
    const int b  = bh >> 6;
    const int h  = bh & 63;
    const int cbase = blockIdx.y << 7;   // 0 or 128
    const int tid = threadIdx.x;
    const int w   = tid & 63;
    const int s   = tid >> 6;            // channel slice 0/1

    __shared__ __align__(16) float sbuf[NBUF][Kk][NCH][SROW];

    const float4* xb4 = (const float4*)(x + (size_t)b * Cc * Hc * Wc);
    float*        ob  = out + (size_t)b * Cc * (Hc * 2) * (Wc * 2);

    // ---- staging tasks: 5 fixed cp.async(16B) per thread ----
    const uint32_t sb_u32 = (uint32_t)__cvta_generic_to_shared(&sbuf[0][0][0][0]);
    int      sidx[NTASK];     // global float4 index (advances CPC channels per issue)
    uint32_t sdst[NTASK];     // smem byte address within buffer 0
    bool     svalid[NTASK];
    #pragma unroll
    for (int k = 0; k < NTASK; k++) {
        int e  = tid + k * THREADS;      // 0..639
        int f  = e & 15;                 // float4 column (gc = 4f)
        int rc = e >> 4;                 // 0..39
        int r  = rc >> 3;                // 0..4
        int ci = rc & 7;                 // 0..7
        int gr = h - 2 + r;
        int ch = cbase + ((ci >> 2) << 6) + (ci & 3);
        svalid[k] = (unsigned)gr < (unsigned)Hc;
        sidx[k]   = ch * (Hc * Wc / 4) + gr * (Wc / 4) + f;
        sdst[k]   = sb_u32 + ((r * NCH + ci) * SROW + 4 * f + 4) * 4;
    }

    // ---- prologue: issue staging groups 0 and 1 immediately ----
    #pragma unroll
    for (int k = 0; k < NTASK; k++) cp_async16(sdst[k],            xb4 + sidx[k], svalid[k]);
    cp_commit();
    #pragma unroll
    for (int k = 0; k < NTASK; k++) { sidx[k] += CH4STRIDE;
                                      cp_async16(sdst[k] + BUFBYTES, xb4 + sidx[k], svalid[k]); }
    cp_commit();

    // ---- zero halo/pad columns (cols 0..3, 68..71 of all NBUF buffers) ----
    for (int e = tid; e < NBUF * Kk * NCH * 8; e += THREADS) {
        int rc = e >> 3, cs = e & 7;
        int col = (cs < 4) ? cs : (64 + cs);
        (&sbuf[0][0][0][0])[rc * SROW + col] = 0.f;
    }

    // ---- 100 reassembly weights -> registers (overlaps in-flight staging) ----
    float wreg[QQ];
    const float* kmp = km + ((size_t)b * QQ * Hc + h) * Wc + w;
    #pragma unroll
    for (int q = 0; q < QQ; q++)
        wreg[q] = __ldg(kmp + (size_t)q * (Hc * Wc));

    float* optr = ob + ((size_t)(cbase + (s << 6)) * 128 + 2 * h) * 128 + 2 * w;
    const float* sbgen = &sbuf[0][0][0][0];
    int rdBuf = 0;   // compute(i) reads buf[i%3]; issue(i+2) writes buf[(i+2)%3]

    #pragma unroll 1
    for (int i = 0; i < NITER; i++) {
        if (i < NITER - 1) cp_wait<1>(); else cp_wait<0>();
        __syncthreads();   // (a) group-i data visible to all; (b) all readers of
                           //     iter i-1 are past -> safe to overwrite buf[(i+2)%3]

        if (i + 2 < NITER) {
            int wrBuf = rdBuf + 2; if (wrBuf >= NBUF) wrBuf -= NBUF;
            uint32_t wOff = (uint32_t)wrBuf * BUFBYTES;
            #pragma unroll
            for (int k = 0; k < NTASK; k++) {
                sidx[k] += CH4STRIDE;
                cp_async16(sdst[k] + wOff, xb4 + sidx[k], svalid[k]);
            }
            cp_commit();
        }

        // ---- compute CPC channels for this thread's slice ----
        const float* base = sbgen + rdBuf * BUFFLOATS + (s * CPC) * SROW + (w + 2);
        #pragma unroll
        for (int kch = 0; kch < CPC; kch++) {
            const float* sp = base + kch * SROW;
            float a0 = 0.f, a1 = 0.f, a2 = 0.f, a3 = 0.f;
            #pragma unroll
            for (int r = 0; r < Kk; r++) {
                const float* rp = sp + r * (NCH * SROW);
                float x0 = rp[0], x1 = rp[1], x2 = rp[2], x3 = rp[3], x4 = rp[4];
                const int wb = r * Kk;
                a0 = fmaf(wreg[wb+0],    x0, a0); a0 = fmaf(wreg[wb+1],    x1, a0);
                a0 = fmaf(wreg[wb+2],    x2, a0); a0 = fmaf(wreg[wb+3],    x3, a0);
                a0 = fmaf(wreg[wb+4],    x4, a0);
                a1 = fmaf(wreg[25+wb+0], x0, a1); a1 = fmaf(wreg[25+wb+1], x1, a1);
                a1 = fmaf(wreg[25+wb+2], x2, a1); a1 = fmaf(wreg[25+wb+3], x3, a1);
                a1 = fmaf(wreg[25+wb+4], x4, a1);
                a2 = fmaf(wreg[50+wb+0], x0, a2); a2 = fmaf(wreg[50+wb+1], x1, a2);
                a2 = fmaf(wreg[50+wb+2], x2, a2); a2 = fmaf(wreg[50+wb+3], x3, a2);
                a2 = fmaf(wreg[50+wb+4], x4, a2);
                a3 = fmaf(wreg[75+wb+0], x0, a3); a3 = fmaf(wreg[75+wb+1], x1, a3);
                a3 = fmaf(wreg[75+wb+2], x2, a3); a3 = fmaf(wreg[75+wb+3], x3, a3);
                a3 = fmaf(wreg[75+wb+4], x4, a3);
            }
            // subpixel u = i*2+j -> (2h+i, 2w+j)
            *reinterpret_cast<float2*>(optr)       = make_float2(a0, a1);
            *reinterpret_cast<float2*>(optr + 128) = make_float2(a2, a3);
            optr += 128 * 128;
        }

        rdBuf++; if (rdBuf == NBUF) rdBuf = 0;
    }
}

extern "C" void kernel_launch(void* const* d_in, const int* in_sizes, int n_in,
                              void* d_out, int out_size)
{
    const float* x  = (const float*)d_in[0];   // [8,256,64,64]
    const float* km = (const float*)d_in[1];   // [8,100,64,64]
    float* out = (float*)d_out;                // [8,256,128,128]

    dim3 grid(Bc * Hc, 2);
    carafe_kernel<<<grid, THREADS>>>(x, km, out);
}